// round 13
// baseline (speedup 1.0000x reference)
#include <cuda_runtime.h>
#include <cuda_fp16.h>

#define NUSERS 100000
#define NITEMS 50000
#define NNODES 150000
#define NEDGES 1200000
#define NH4    (NNODES * 8)         // uint4 (8-half) slots per fp16 buffer
#define SCAN_B 1024
#define NBLK   ((NNODES + SCAN_B - 1) / SCAN_B)   // 147

// fp16 embedding buffers (3 x 19.2 MB -> working set L2-resident) + CSR.
// Zero-state protocol (every call leaves arrays zeroed for the next call):
// g_cnt zeroed by k_reorder epilogue, g_pos by k_prop0 epilogue, g_done by
// k_scan1's finalizer block. First call relies on static zero-init.
__device__ __align__(16) uint4 g_h0[NH4];
__device__ __align__(16) uint4 g_h1[NH4];
__device__ __align__(16) uint4 g_h2[NH4];
__device__ int  g_cnt[NNODES];
__device__ int  g_pos[NNODES];
__device__ int  g_rowptr[NNODES + 1];
__device__ int  g_bsum[NBLK];
__device__ int  g_done;
__device__ __align__(8) int2 g_edges[NEDGES];   // {col, half2(0.8v, 0.8v) bits}

__device__ __forceinline__ __half2 as_h2(unsigned u) {
    return *reinterpret_cast<__half2*>(&u);
}

// ---- fp16 pack helper for init (fp32 -> fp16 storage) ----
__device__ __forceinline__ uint4 pack8(const float* f) {
    uint4 x;
    *reinterpret_cast<__half2*>(&x.x) = __floats2half2_rn(f[0], f[1]);
    *reinterpret_cast<__half2*>(&x.y) = __floats2half2_rn(f[2], f[3]);
    *reinterpret_cast<__half2*>(&x.z) = __floats2half2_rn(f[4], f[5]);
    *reinterpret_cast<__half2*>(&x.w) = __floats2half2_rn(f[6], f[7]);
    return x;
}

// h0 = fp16(concat(user_emb, item_emb)), fused with the row histogram.
// g_cnt is already zero at entry (static init / previous call's epilogue).
__global__ __launch_bounds__(256) void k_inithist(const float* __restrict__ ue,
                                                  const float* __restrict__ ie,
                                                  const int* __restrict__ er) {
    int i = blockIdx.x * 256 + threadIdx.x;
    if (i < NEDGES) atomicAdd(&g_cnt[er[i]], 1);
    if (i >= NH4) return;
    const float4* src = (i < NUSERS * 8) ? (const float4*)ue : (const float4*)ie;
    int j = (i < NUSERS * 8) ? i : i - NUSERS * 8;
    float4 p = src[2 * j];
    float4 q = src[2 * j + 1];
    float f[8] = {p.x, p.y, p.z, p.w, q.x, q.y, q.z, q.w};
    g_h0[i] = pack8(f);
}

// Coalesced per-block scan of g_cnt -> g_rowptr; fused block-total scan
// (last-arriving block converts g_bsum to exclusive prefix, resets g_done).
__global__ __launch_bounds__(SCAN_B) void k_scan1() {
    __shared__ int sh[SCAN_B];
    __shared__ int s_last;
    int idx = blockIdx.x * SCAN_B + threadIdx.x;
    int v = (idx < NNODES) ? g_cnt[idx] : 0;
    sh[threadIdx.x] = v;
    __syncthreads();
    #pragma unroll
    for (int o = 1; o < SCAN_B; o <<= 1) {
        int t = (threadIdx.x >= o) ? sh[threadIdx.x - o] : 0;
        __syncthreads();
        sh[threadIdx.x] += t;
        __syncthreads();
    }
    int incl = sh[threadIdx.x];
    if (idx <= NNODES) g_rowptr[idx] = incl - v;
    if (threadIdx.x == SCAN_B - 1) g_bsum[blockIdx.x] = incl;

    __threadfence();
    if (threadIdx.x == 0) s_last = (atomicAdd(&g_done, 1) == NBLK - 1);
    __syncthreads();
    if (s_last) {
        int i = threadIdx.x;
        int bv = (i < NBLK) ? g_bsum[i] : 0;
        sh[i] = bv;
        __syncthreads();
        #pragma unroll
        for (int o = 1; o < SCAN_B; o <<= 1) {
            int t = (i >= o) ? sh[i - o] : 0;
            __syncthreads();
            sh[i] += t;
            __syncthreads();
        }
        if (i < NBLK) g_bsum[i] = sh[i] - bv;
        if (i == 0) g_done = 0;
    }
}

__device__ __forceinline__ void row_range(int row, int& beg, int& end) {
    beg = g_rowptr[row]     + g_bsum[row >> 10];
    end = g_rowptr[row + 1] + g_bsum[(row + 1) >> 10];
}

// Place edges into row segments, 4 edges/thread; weight stored as broadcast
// half2 of 0.8*val (one conversion here, zero in the prop hot loop).
// Epilogue re-zeroes g_cnt for the next call.
__global__ __launch_bounds__(256) void k_reorder(const int* __restrict__ er,
                                                 const int* __restrict__ ec,
                                                 const float* __restrict__ ev) {
    int t = blockIdx.x * 256 + threadIdx.x;
    int b = blockIdx.x * 1024 + threadIdx.x;
    #pragma unroll
    for (int j = 0; j < 4; j++) {
        int e = b + j * 256;
        if (e < NEDGES) {
            int row  = er[e];
            int base = g_rowptr[row] + g_bsum[row >> 10];
            int pos  = base + atomicAdd(&g_pos[row], 1);
            __half2 vh = __float2half2_rn(ev[e] * 0.8f);
            g_edges[pos] = make_int2(ec[e], *reinterpret_cast<int*>(&vh));
        }
    }
    if (t < NNODES) g_cnt[t] = 0;
}

// dst[row] = fp16( 0.2*src[row] + sum 0.8v*src[col] )
// 8 lanes/row, one dense 128B line per row-group gather; ALL-fp16 HFMA2
// accumulation -> per edge-lane: 1 LDG.128 + 4 HFMA2, zero conversions.
template <int ZERO_POS>
__device__ __forceinline__ void prop_body(const uint4* __restrict__ src,
                                          uint4* __restrict__ dst) {
    int t = blockIdx.x * 256 + threadIdx.x;        // NNODES*8 threads
    if (ZERO_POS && t < NNODES) g_pos[t] = 0;
    int row = t >> 3;
    if (row >= NNODES) return;
    int sub  = t & 7;
    int base = row * 8 + sub;
    int beg, end; row_range(row, beg, end);

    const __half2 k2 = __float2half2_rn(0.2f);
    uint4 o = src[base];
    __half2 s0 = __hmul2(k2, as_h2(o.x));
    __half2 s1 = __hmul2(k2, as_h2(o.y));
    __half2 s2 = __hmul2(k2, as_h2(o.z));
    __half2 s3 = __hmul2(k2, as_h2(o.w));

    int e  = beg;
    int n4 = beg + ((end - beg) & ~3);
    for (; e < n4; e += 4) {                       // 4 gathers in flight
        int2 p0 = g_edges[e];
        int2 p1 = g_edges[e + 1];
        int2 p2 = g_edges[e + 2];
        int2 p3 = g_edges[e + 3];
        uint4 x0 = src[p0.x * 8 + sub];
        uint4 x1 = src[p1.x * 8 + sub];
        uint4 x2 = src[p2.x * 8 + sub];
        uint4 x3 = src[p3.x * 8 + sub];
        __half2 v0 = as_h2((unsigned)p0.y);
        __half2 v1 = as_h2((unsigned)p1.y);
        __half2 v2 = as_h2((unsigned)p2.y);
        __half2 v3 = as_h2((unsigned)p3.y);
        s0 = __hfma2(v0, as_h2(x0.x), s0); s1 = __hfma2(v0, as_h2(x0.y), s1);
        s2 = __hfma2(v0, as_h2(x0.z), s2); s3 = __hfma2(v0, as_h2(x0.w), s3);
        s0 = __hfma2(v1, as_h2(x1.x), s0); s1 = __hfma2(v1, as_h2(x1.y), s1);
        s2 = __hfma2(v1, as_h2(x1.z), s2); s3 = __hfma2(v1, as_h2(x1.w), s3);
        s0 = __hfma2(v2, as_h2(x2.x), s0); s1 = __hfma2(v2, as_h2(x2.y), s1);
        s2 = __hfma2(v2, as_h2(x2.z), s2); s3 = __hfma2(v2, as_h2(x2.w), s3);
        s0 = __hfma2(v3, as_h2(x3.x), s0); s1 = __hfma2(v3, as_h2(x3.y), s1);
        s2 = __hfma2(v3, as_h2(x3.z), s2); s3 = __hfma2(v3, as_h2(x3.w), s3);
    }
    for (; e < end; e++) {
        int2 p = g_edges[e];
        uint4 x = src[p.x * 8 + sub];
        __half2 v = as_h2((unsigned)p.y);
        s0 = __hfma2(v, as_h2(x.x), s0); s1 = __hfma2(v, as_h2(x.y), s1);
        s2 = __hfma2(v, as_h2(x.z), s2); s3 = __hfma2(v, as_h2(x.w), s3);
    }
    uint4 outv;
    outv.x = *reinterpret_cast<unsigned*>(&s0);
    outv.y = *reinterpret_cast<unsigned*>(&s1);
    outv.z = *reinterpret_cast<unsigned*>(&s2);
    outv.w = *reinterpret_cast<unsigned*>(&s3);
    dst[base] = outv;
}

__global__ __launch_bounds__(256) void k_prop0() { prop_body<1>(g_h0, g_h1); }
__global__ __launch_bounds__(256) void k_prop1() { prop_body<0>(g_h1, g_h2); }

// acc(n) = e0+e1+e2+e3 in fp32, e3 on the fly from fp16 e2; one half2 per lane.
__device__ __forceinline__ float2 node_acc(int n, int lane) {
    const unsigned* __restrict__ H0 = (const unsigned*)g_h0;
    const unsigned* __restrict__ H1 = (const unsigned*)g_h1;
    const unsigned* __restrict__ H2 = (const unsigned*)g_h2;
    int idx = n * 32 + lane;
    float2 z0 = __half22float2(as_h2(H0[idx]));
    float2 z1 = __half22float2(as_h2(H1[idx]));
    float2 z2 = __half22float2(as_h2(H2[idx]));
    float2 z3 = make_float2(0.2f * z2.x, 0.2f * z2.y);
    int beg, end; row_range(n, beg, end);
    int e  = beg;
    int n4 = beg + ((end - beg) & ~3);
    for (; e < n4; e += 4) {
        int2 p0 = g_edges[e];
        int2 p1 = g_edges[e + 1];
        int2 p2 = g_edges[e + 2];
        int2 p3 = g_edges[e + 3];
        float2 x0 = __half22float2(as_h2(H2[p0.x * 32 + lane]));
        float2 x1 = __half22float2(as_h2(H2[p1.x * 32 + lane]));
        float2 x2 = __half22float2(as_h2(H2[p2.x * 32 + lane]));
        float2 x3 = __half22float2(as_h2(H2[p3.x * 32 + lane]));
        float v0 = __low2float(as_h2((unsigned)p0.y));
        float v1 = __low2float(as_h2((unsigned)p1.y));
        float v2 = __low2float(as_h2((unsigned)p2.y));
        float v3 = __low2float(as_h2((unsigned)p3.y));
        z3.x += v0 * x0.x; z3.y += v0 * x0.y;
        z3.x += v1 * x1.x; z3.y += v1 * x1.y;
        z3.x += v2 * x2.x; z3.y += v2 * x2.y;
        z3.x += v3 * x3.x; z3.y += v3 * x3.y;
    }
    for (; e < end; e++) {
        int2 p = g_edges[e];
        float2 x = __half22float2(as_h2(H2[p.x * 32 + lane]));
        float v = __low2float(as_h2((unsigned)p.y));
        z3.x += v * x.x; z3.y += v * x.y;
    }
    return make_float2(z0.x + z1.x + z2.x + z3.x, z0.y + z1.y + z2.y + z3.y);
}

// gamma[w] = dot(acc(u), acc(NUSERS+i)) / 16
__global__ __launch_bounds__(256) void k_gamma(const int* __restrict__ users,
                                               const int* __restrict__ items,
                                               float* __restrict__ out) {
    int w    = (blockIdx.x * 256 + threadIdx.x) >> 5;
    int lane = threadIdx.x & 31;
    if (w >= 4096) return;
    float2 a = node_acc(users[w],          lane);
    float2 b = node_acc(NUSERS + items[w], lane);
    float s = a.x * b.x + a.y * b.y;
    #pragma unroll
    for (int o = 16; o; o >>= 1) s += __shfl_xor_sync(0xffffffffu, s, o);
    if (lane == 0) out[w] = s * (1.0f / 16.0f);
}

extern "C" void kernel_launch(void* const* d_in, const int* in_sizes, int n_in,
                              void* d_out, int out_size) {
    const int*   users = (const int*)  d_in[0];
    const int*   items = (const int*)  d_in[1];
    const int*   er    = (const int*)  d_in[2];
    const int*   ec    = (const int*)  d_in[3];
    const float* ev    = (const float*)d_in[4];
    const float* ue    = (const float*)d_in[5];
    const float* ie    = (const float*)d_in[6];
    float* out = (float*)d_out;

    const int INIT_BLOCKS = (NH4 + 255) / 256;            // 4688 (covers NEDGES too)
    const int PROP_BLOCKS = (NNODES * 8 + 255) / 256;     // 4688
    const int REO_BLOCKS  = (NEDGES + 1023) / 1024;       // 1172

    k_inithist<<<INIT_BLOCKS, 256>>>(ue, ie, er);
    k_scan1<<<NBLK, SCAN_B>>>();
    k_reorder<<<REO_BLOCKS, 256>>>(er, ec, ev);
    k_prop0<<<PROP_BLOCKS, 256>>>();                      // ncu capture slot
    k_prop1<<<PROP_BLOCKS, 256>>>();
    k_gamma<<<4096 / 8, 256>>>(users, items, out);
}